// round 4
// baseline (speedup 1.0000x reference)
#include <cuda_runtime.h>
#include <math.h>

// ---------------- problem constants ----------------
#define Bc   8
#define Nn   64
#define Dd   128
#define Hh   4
#define DHc  32
#define FFc  512
#define Lc   3
#define TOK  (Bc*Nn*Nn)              // 32768 tokens
#define SCALE_INV 0.17677669529663687f   // 1/sqrt(32)

// ---------------- device scratch (allowed: __device__ globals) ----------------
__device__ float g_tok[TOK*Dd];          // 16 MB
__device__ float g_q  [TOK*Dd];
__device__ float g_k  [TOK*Dd];
__device__ float g_v1 [TOK*Dd];
__device__ float g_v2 [TOK*Dd];
__device__ float g_s  [Bc*Hh*Nn*Nn*Nn]; // 33.5 MB, layout [b][h][l][i][j]
__device__ float g_o  [TOK*Dd];
__device__ float g_hid[TOK*FFc];        // 64 MB

// ---------------- embedding: build initial tok ----------------
__global__ void embed_kernel(const float* __restrict__ x,
                             const float* __restrict__ ea,
                             const unsigned int* __restrict__ mask,
                             const float* __restrict__ nW, const float* __restrict__ nb,
                             const float* __restrict__ eW, const float* __restrict__ eb,
                             const float* __restrict__ noe)
{
    int tkn = blockIdx.x;            // (b,i,j)
    int b   = tkn >> 12;
    int ij  = tkn & 4095;
    int i   = ij >> 6, j = ij & 63;
    int d   = threadIdx.x;           // 0..127
    __shared__ float s_in[16];
    float out;
    if (i == j) {
        if (d < 16) s_in[d] = x[(b*Nn + i)*16 + d];
        __syncthreads();
        float acc = nb[d];
#pragma unroll
        for (int c = 0; c < 16; c++) acc += s_in[c] * nW[c*Dd + d];
        out = acc;
    } else {
        if (d < 8) s_in[d] = ea[tkn*8 + d];
        __syncthreads();
        if (mask[tkn] != 0u) {
            float acc = eb[d];
#pragma unroll
            for (int c = 0; c < 8; c++) acc += s_in[c] * eW[c*Dd + d];
            out = acc;
        } else {
            out = noe[d];
        }
    }
    g_tok[tkn*Dd + d] = out;
}

// ---------------- generic 128x128 SGEMM, BK=8, 8x8 per thread ----------------
// C[M x N] = A[M x K] @ W[K x N]  (+bias) (+residual) (ReLU) (LayerNorm over N=128)
template<bool RELU, bool RESID, bool LN>
__global__ void __launch_bounds__(256, 2)
gemm128(const float* __restrict__ A, const float* __restrict__ W,
        const float* __restrict__ bias, const float* __restrict__ resid,
        const float* __restrict__ lng,  const float* __restrict__ lnb,
        float* __restrict__ C, int K, int N)
{
    __shared__ float As[8][128];
    __shared__ float Bs[8][128];
    const int t   = threadIdx.x;
    const int bm0 = blockIdx.y * 128;
    const int bn0 = blockIdx.x * 128;
    const int tx  = t & 15, ty = t >> 4;

    float acc[8][8];
#pragma unroll
    for (int i = 0; i < 8; i++)
#pragma unroll
        for (int j = 0; j < 8; j++) acc[i][j] = 0.f;

    const int am  = t >> 1;
    const int akq = (t & 1) * 4;
    const int bkr = t >> 5;
    const int bnc = (t & 31) * 4;
    const float* Aptr = A + (size_t)(bm0 + am) * K + akq;
    const float* Wptr = W + (size_t)bkr * N + bn0 + bnc;

    for (int k0 = 0; k0 < K; k0 += 8) {
        float4 av = *(const float4*)(Aptr + k0);
        float4 wv = *(const float4*)(Wptr + (size_t)k0 * N);
        As[akq+0][am] = av.x; As[akq+1][am] = av.y;
        As[akq+2][am] = av.z; As[akq+3][am] = av.w;
        *(float4*)&Bs[bkr][bnc] = wv;
        __syncthreads();
#pragma unroll
        for (int kk = 0; kk < 8; kk++) {
            float4 a0 = *(const float4*)&As[kk][ty*8];
            float4 a1 = *(const float4*)&As[kk][ty*8+4];
            float4 b0 = *(const float4*)&Bs[kk][tx*8];
            float4 b1 = *(const float4*)&Bs[kk][tx*8+4];
            float a[8] = {a0.x,a0.y,a0.z,a0.w,a1.x,a1.y,a1.z,a1.w};
            float bb[8] = {b0.x,b0.y,b0.z,b0.w,b1.x,b1.y,b1.z,b1.w};
#pragma unroll
            for (int i = 0; i < 8; i++)
#pragma unroll
                for (int j = 0; j < 8; j++)
                    acc[i][j] += a[i] * bb[j];
        }
        __syncthreads();
    }

    const int col0 = bn0 + tx*8;
    float bv[8];
#pragma unroll
    for (int j = 0; j < 8; j++) bv[j] = (bias != nullptr) ? bias[col0 + j] : 0.f;

#pragma unroll
    for (int i = 0; i < 8; i++) {
        int row = bm0 + ty*8 + i;
        float v[8];
        if (RESID) {
            float4 r0 = *(const float4*)&resid[(size_t)row*N + col0];
            float4 r1 = *(const float4*)&resid[(size_t)row*N + col0 + 4];
            float rr[8] = {r0.x,r0.y,r0.z,r0.w,r1.x,r1.y,r1.z,r1.w};
#pragma unroll
            for (int j = 0; j < 8; j++) v[j] = acc[i][j] + bv[j] + rr[j];
        } else {
#pragma unroll
            for (int j = 0; j < 8; j++) v[j] = acc[i][j] + bv[j];
        }
        if (RELU) {
#pragma unroll
            for (int j = 0; j < 8; j++) v[j] = fmaxf(v[j], 0.f);
        }
        if (LN) {
            // full row (128 cols) spread over the 16 lanes sharing this ty
            float s1 = 0.f, s2 = 0.f;
#pragma unroll
            for (int j = 0; j < 8; j++) { s1 += v[j]; s2 += v[j]*v[j]; }
#pragma unroll
            for (int m = 8; m > 0; m >>= 1) {
                s1 += __shfl_xor_sync(0xffffffffu, s1, m);
                s2 += __shfl_xor_sync(0xffffffffu, s2, m);
            }
            float mean = s1 * (1.f/128.f);
            float var  = s2 * (1.f/128.f) - mean*mean;
            float rstd = rsqrtf(var + 1e-5f);
#pragma unroll
            for (int j = 0; j < 8; j++)
                v[j] = (v[j] - mean) * rstd * lng[col0 + j] + lnb[col0 + j];
        }
        *(float4*)&C[(size_t)row*N + col0]     = make_float4(v[0],v[1],v[2],v[3]);
        *(float4*)&C[(size_t)row*N + col0 + 4] = make_float4(v[4],v[5],v[6],v[7]);
    }
}

// ---------------- attention scores: per (b,h,l): s[i][j] = q_i . k_j / SCALE ----
__global__ void __launch_bounds__(256) attn_s_kernel()
{
    const int l = blockIdx.x, h = blockIdx.y, b = blockIdx.z;
    __shared__ float Qs[32][64];   // [d][i]
    __shared__ float Ks[32][64];   // [d][j]
    const int t = threadIdx.x;
    {
        int r  = t >> 2;           // 0..63
        int dq = (t & 3) * 8;      // 0,8,16,24
        const float* qp = g_q + ((size_t)((b*Nn + r)*Nn + l))*Dd + h*DHc + dq;
        const float* kp = g_k + ((size_t)((b*Nn + l)*Nn + r))*Dd + h*DHc + dq;
        float4 q0 = *(const float4*)qp, q1 = *(const float4*)(qp+4);
        float4 k0 = *(const float4*)kp, k1 = *(const float4*)(kp+4);
        Qs[dq+0][r]=q0.x; Qs[dq+1][r]=q0.y; Qs[dq+2][r]=q0.z; Qs[dq+3][r]=q0.w;
        Qs[dq+4][r]=q1.x; Qs[dq+5][r]=q1.y; Qs[dq+6][r]=q1.z; Qs[dq+7][r]=q1.w;
        Ks[dq+0][r]=k0.x; Ks[dq+1][r]=k0.y; Ks[dq+2][r]=k0.z; Ks[dq+3][r]=k0.w;
        Ks[dq+4][r]=k1.x; Ks[dq+5][r]=k1.y; Ks[dq+6][r]=k1.z; Ks[dq+7][r]=k1.w;
    }
    __syncthreads();
    const int tx = t & 15, ty = t >> 4;
    float acc[4][4];
#pragma unroll
    for (int i = 0; i < 4; i++)
#pragma unroll
        for (int j = 0; j < 4; j++) acc[i][j] = 0.f;
#pragma unroll
    for (int d = 0; d < 32; d++) {
        float4 a = *(const float4*)&Qs[d][ty*4];
        float4 c = *(const float4*)&Ks[d][tx*4];
        float av[4] = {a.x,a.y,a.z,a.w};
        float cv[4] = {c.x,c.y,c.z,c.w};
#pragma unroll
        for (int i = 0; i < 4; i++)
#pragma unroll
            for (int j = 0; j < 4; j++)
                acc[i][j] += av[i]*cv[j];
    }
    float* sp = g_s + ((size_t)((b*Hh + h)*Nn + l)) * 4096;
#pragma unroll
    for (int i = 0; i < 4; i++) {
        *(float4*)&sp[(ty*4 + i)*64 + tx*4] =
            make_float4(acc[i][0]*SCALE_INV, acc[i][1]*SCALE_INV,
                        acc[i][2]*SCALE_INV, acc[i][3]*SCALE_INV);
    }
}

// ---------------- softmax over l + o = sum_l a * (v1 ⊙ v2), per (b,h,i) --------
__global__ void __launch_bounds__(256) attn_ao_kernel()
{
    const int i = blockIdx.x, h = blockIdx.y, b = blockIdx.z;
    __shared__ float Aa[64][64];       // [l][j]
    __shared__ float V1s[64][32];      // [l][d]
    __shared__ float redA[4][64];
    __shared__ float redB[4][64];
    const int t = threadIdx.x;

    // ---- softmax: thread (j = t&63, g = t>>6) handles l in [g*16, g*16+16) ----
    {
        const int j = t & 63, g = t >> 6;
        const float* sp = g_s + ((size_t)(b*Hh + h)*Nn) * 4096 + i*64 + j;
        float sv[16];
#pragma unroll
        for (int u = 0; u < 16; u++) sv[u] = sp[(size_t)(g*16 + u) * 4096];
        float m = sv[0];
#pragma unroll
        for (int u = 1; u < 16; u++) m = fmaxf(m, sv[u]);
        redA[g][j] = m;
        __syncthreads();
        float cm = fmaxf(fmaxf(redA[0][j], redA[1][j]), fmaxf(redA[2][j], redA[3][j]));
        float lsum = 0.f;
#pragma unroll
        for (int u = 0; u < 16; u++) { sv[u] = __expf(sv[u] - cm); lsum += sv[u]; }
        redB[g][j] = lsum;
        __syncthreads();
        float inv = 1.f / (redB[0][j] + redB[1][j] + redB[2][j] + redB[3][j]);
#pragma unroll
        for (int u = 0; u < 16; u++) Aa[g*16 + u][j] = sv[u] * inv;
    }
    // ---- stage v1[b,i,l,h,:] -> V1s[l][d] ----
    {
        int l  = t >> 2;
        int dq = (t & 3) * 8;
        const float* vp = g_v1 + ((size_t)((b*Nn + i)*Nn + l))*Dd + h*DHc + dq;
        *(float4*)&V1s[l][dq]   = *(const float4*)vp;
        *(float4*)&V1s[l][dq+4] = *(const float4*)(vp + 4);
    }
    __syncthreads();

    // ---- accumulate o: thread (jj = t>>2, dq = (t&3)*8) owns 8 d-values -------
    const int jj = t >> 2;
    const int dq = (t & 3) * 8;
    float acc[8];
#pragma unroll
    for (int u = 0; u < 8; u++) acc[u] = 0.f;
    const float* v2base = g_v2 + ((size_t)(b*Nn)*Nn + jj)*Dd + h*DHc + dq;
#pragma unroll 4
    for (int l = 0; l < 64; l++) {
        float av = Aa[l][jj];
        float4 w0 = *(const float4*)&V1s[l][dq];
        float4 w1 = *(const float4*)&V1s[l][dq+4];
        float4 u0 = *(const float4*)(v2base + (size_t)l*Nn*Dd);
        float4 u1 = *(const float4*)(v2base + (size_t)l*Nn*Dd + 4);
        acc[0] += av * (w0.x * u0.x);
        acc[1] += av * (w0.y * u0.y);
        acc[2] += av * (w0.z * u0.z);
        acc[3] += av * (w0.w * u0.w);
        acc[4] += av * (w1.x * u1.x);
        acc[5] += av * (w1.y * u1.y);
        acc[6] += av * (w1.z * u1.z);
        acc[7] += av * (w1.w * u1.w);
    }
    float* op = g_o + ((size_t)((b*Nn + i)*Nn + jj))*Dd + h*DHc + dq;
    *(float4*)op       = make_float4(acc[0],acc[1],acc[2],acc[3]);
    *(float4*)(op + 4) = make_float4(acc[4],acc[5],acc[6],acc[7]);
}

// ---------------- final readout: diag tokens @ Wout + bout ----------------
__global__ void out_kernel(const float* __restrict__ Wout,
                           const float* __restrict__ bout,
                           float* __restrict__ out)
{
    int w    = (blockIdx.x * blockDim.x + threadIdx.x) >> 5;
    int lane = threadIdx.x & 31;
    if (w >= Bc*Nn) return;
    int b = w >> 6, n = w & 63;
    const float* tp = g_tok + ((size_t)((b*Nn + n)*Nn + n)) * Dd;
    float4 tv = *(const float4*)(tp + lane*4);
    float4 wv = *(const float4*)(Wout + lane*4);
    float s = tv.x*wv.x + tv.y*wv.y + tv.z*wv.z + tv.w*wv.w;
#pragma unroll
    for (int m = 16; m > 0; m >>= 1) s += __shfl_xor_sync(0xffffffffu, s, m);
    if (lane == 0) out[w] = s + bout[0];
}

// ---------------- host launcher ----------------
extern "C" void kernel_launch(void* const* d_in, const int* in_sizes, int n_in,
                              void* d_out, int out_size)
{
    const float*        x        = (const float*)d_in[0];
    const float*        ea       = (const float*)d_in[1];
    const unsigned int* mask     = (const unsigned int*)d_in[2];
    const float*        node_W   = (const float*)d_in[3];
    const float*        node_b   = (const float*)d_in[4];
    const float*        edge_W   = (const float*)d_in[5];
    const float*        edge_b   = (const float*)d_in[6];
    const float*        no_edge  = (const float*)d_in[7];
    const float*        Wq       = (const float*)d_in[8];
    const float*        Wk       = (const float*)d_in[9];
    const float*        Wv1      = (const float*)d_in[10];
    const float*        Wv2      = (const float*)d_in[11];
    const float*        Wo       = (const float*)d_in[12];
    const float*        bo       = (const float*)d_in[13];
    const float*        ln1g     = (const float*)d_in[14];
    const float*        ln1b     = (const float*)d_in[15];
    const float*        W1       = (const float*)d_in[16];
    const float*        b1       = (const float*)d_in[17];
    const float*        W2       = (const float*)d_in[18];
    const float*        b2       = (const float*)d_in[19];
    const float*        ln2g     = (const float*)d_in[20];
    const float*        ln2b     = (const float*)d_in[21];
    const float*        Wout     = (const float*)d_in[22];
    const float*        bout     = (const float*)d_in[23];

    float *tok, *q, *k, *v1, *v2, *o, *hid;
    cudaGetSymbolAddress((void**)&tok, g_tok);
    cudaGetSymbolAddress((void**)&q,   g_q);
    cudaGetSymbolAddress((void**)&k,   g_k);
    cudaGetSymbolAddress((void**)&v1,  g_v1);
    cudaGetSymbolAddress((void**)&v2,  g_v2);
    cudaGetSymbolAddress((void**)&o,   g_o);
    cudaGetSymbolAddress((void**)&hid, g_hid);

    embed_kernel<<<TOK, 128>>>(x, ea, mask, node_W, node_b, edge_W, edge_b, no_edge);

    const dim3 g1(1, TOK/128);    // N=128
    const dim3 g4(4, TOK/128);    // N=512
    const dim3 ga(Nn, Hh, Bc);

    for (int l = 0; l < Lc; l++) {
        size_t wOff  = (size_t)l * Dd * Dd;
        size_t bOff  = (size_t)l * Dd;
        size_t w1Off = (size_t)l * Dd * FFc;
        size_t b1Off = (size_t)l * FFc;

        gemm128<false,false,false><<<g1,256>>>(tok, Wq  + wOff, nullptr, nullptr, nullptr, nullptr, q,  Dd, Dd);
        gemm128<false,false,false><<<g1,256>>>(tok, Wk  + wOff, nullptr, nullptr, nullptr, nullptr, k,  Dd, Dd);
        gemm128<false,false,false><<<g1,256>>>(tok, Wv1 + wOff, nullptr, nullptr, nullptr, nullptr, v1, Dd, Dd);
        gemm128<false,false,false><<<g1,256>>>(tok, Wv2 + wOff, nullptr, nullptr, nullptr, nullptr, v2, Dd, Dd);

        attn_s_kernel <<<ga,256>>>();
        attn_ao_kernel<<<ga,256>>>();

        // tok = LN(tok + o @ Wo + bo)
        gemm128<false,true,true><<<g1,256>>>(o, Wo + wOff, bo + bOff, tok,
                                             ln1g + bOff, ln1b + bOff, tok, Dd, Dd);
        // hid = relu(tok @ W1 + b1)
        gemm128<true,false,false><<<g4,256>>>(tok, W1 + w1Off, b1 + b1Off,
                                              nullptr, nullptr, nullptr, hid, Dd, FFc);
        // tok = LN(tok + hid @ W2 + b2)
        gemm128<false,true,true><<<g1,256>>>(hid, W2 + w1Off, b2 + bOff, tok,
                                             ln2g + bOff, ln2b + bOff, tok, FFc, Dd);
    }

    out_kernel<<<(Bc*Nn*32 + 255)/256, 256>>>(Wout, bout, (float*)d_out);
}